// round 3
// baseline (speedup 1.0000x reference)
#include <cuda_runtime.h>

#define TILE_S 256
#define TILE_B 32
#define NTHREADS 256
#define NCOEF 8   // GRID_SIZE + SPLINE_ORDER = 5 + 3

__global__ __launch_bounds__(NTHREADS) void bspline_kernel(
    const float* __restrict__ x,
    const float* __restrict__ coef,
    const float* __restrict__ grid,
    float* __restrict__ out,
    int nspl, int batch, int jmax)
{
    // Transposed coefficient tile: cT[k][s_local]; lanes read consecutive
    // s_local for a fixed k -> conflict-free LDS even with dynamic k.
    __shared__ float cT[NCOEF][TILE_S];

    const int tid = threadIdx.x;
    const int s   = blockIdx.x * TILE_S + tid;
    const int b0  = blockIdx.y * TILE_B;

    if (s < nspl) {
        // Each thread loads its own spline's 8 coefficients (32B contiguous,
        // two float4s) and scatters into the transposed SMEM tile.
        const float4* cv = reinterpret_cast<const float4*>(coef + (size_t)s * NCOEF);
        float4 cA = cv[0];
        float4 cB = cv[1];
        cT[0][tid] = cA.x; cT[1][tid] = cA.y; cT[2][tid] = cA.z; cT[3][tid] = cA.w;
        cT[4][tid] = cB.x; cT[5][tid] = cB.y; cT[6][tid] = cB.z; cT[7][tid] = cB.w;
    }

    // Uniform-grid constants: knot[order]=left edge of valid domain, h=spacing.
    const float g3    = __ldg(&grid[3]);
    const float h     = __ldg(&grid[4]) - g3;
    const float inv_h = 1.0f / h;

    __syncthreads();

    if (s >= nspl) return;

    const int rows = min(TILE_B, batch - b0);
    const float* xp = x   + (size_t)b0 * nspl + s;
    float*       op = out + (size_t)b0 * nspl + s;

    #pragma unroll 4
    for (int bi = 0; bi < rows; ++bi) {
        const float xv = xp[(size_t)bi * nspl];

        // Interval index within the valid domain: j in [0, jmax]
        float t = (xv - g3) * inv_h;
        int j = __float2int_rd(t);
        j = max(0, min(jmax, j));
        const float u = t - (float)j;

        // Uniform cubic B-spline basis (only 4 nonzero bases)
        const float omu = 1.0f - u;
        const float u2  = u * u;
        const float u3  = u2 * u;
        const float b0w = omu * omu * omu * (1.0f / 6.0f);
        const float b1w = fmaf(0.5f, u3, (2.0f / 3.0f) - u2);
        const float b2w = fmaf(-0.5f, u3,
                           fmaf(0.5f, u2, fmaf(0.5f, u, 1.0f / 6.0f)));
        const float b3w = u3 * (1.0f / 6.0f);

        // 4-tap dot with dynamically indexed SMEM coefficients
        float r =       b0w * cT[j    ][tid];
        r = fmaf(b1w, cT[j + 1][tid], r);
        r = fmaf(b2w, cT[j + 2][tid], r);
        r = fmaf(b3w, cT[j + 3][tid], r);

        op[(size_t)bi * nspl] = r;
    }
}

extern "C" void kernel_launch(void* const* d_in, const int* in_sizes, int n_in,
                              void* d_out, int out_size)
{
    const float* x    = (const float*)d_in[0];
    const float* coef = (const float*)d_in[1];
    const float* grid = (const float*)d_in[2];
    float* out = (float*)d_out;

    const int nspl  = in_sizes[1] / NCOEF;       // coefficients: (S, 8)
    const int batch = in_sizes[0] / nspl;        // x: (B, S)
    const int jmax  = NCOEF - 4;                 // GRID_SIZE - 1 = 4

    dim3 block(NTHREADS);
    dim3 grd((nspl + TILE_S - 1) / TILE_S, (batch + TILE_B - 1) / TILE_B);
    bspline_kernel<<<grd, block>>>(x, coef, grid, out, nspl, batch, jmax);
}